// round 1
// baseline (speedup 1.0000x reference)
#include <cuda_runtime.h>
#include <math.h>

// ---------------- problem constants ----------------
#define NB   4
#define NS   2048
#define NH   16
#define NHD  128
#define NRD  64
#define NLAT 512
#define NHID 2048
#define NM   (NB*NS)        // 8192 rows total

// ---------------- device scratch (static, allocation-free) ----------------
__device__ float g_qlat [(size_t)NM*NLAT];
__device__ float g_kvlat[(size_t)NM*NLAT];
__device__ float g_krr  [(size_t)NM*NRD];
__device__ float g_qc   [(size_t)NM*1024];
__device__ float g_qr   [(size_t)NM*1024];
__device__ float g_kc   [(size_t)NM*1024];
__device__ float g_V    [(size_t)NM*NHID];
__device__ float g_Q    [(size_t)NM*NHID];
__device__ float g_K    [(size_t)NM*NHID];
__device__ float g_ctx  [(size_t)NM*NHID];

// ---------------- fp32 SGEMM: C[M,N] = A[M,K] @ W[K,N] (+bias) ----------------
// BM=BN=128, BK=16, 256 threads, 8x8 per-thread microtile.
// M is always a multiple of 128 (grid.y covers it); K multiple of 16; N guarded.
template<bool BIAS>
__global__ void __launch_bounds__(256)
sgemm_kernel(const float* __restrict__ A, const float* __restrict__ W,
             float* __restrict__ C, const float* __restrict__ bias,
             int N, int K)
{
    __shared__ float As[16][132];   // transposed A tile, padded
    __shared__ float Bs[16][128];

    const int tid = threadIdx.x;
    const int tx = tid & 15, ty = tid >> 4;
    const int bx = blockIdx.x, by = blockIdx.y;

    const int a_r = tid >> 2;          // 0..63 (row within A tile, +64 for 2nd)
    const int a_c = (tid & 3) << 2;    // 0,4,8,12
    const int b_r = tid >> 5;          // 0..7 (+8 for 2nd)
    const int b_c = (tid & 31) << 2;

    const float* Ab = A + (size_t)by * 128 * K;

    float acc[8][8];
    #pragma unroll
    for (int i = 0; i < 8; i++)
        #pragma unroll
        for (int j = 0; j < 8; j++) acc[i][j] = 0.f;

    for (int k0 = 0; k0 < K; k0 += 16) {
        #pragma unroll
        for (int u = 0; u < 2; u++) {
            int r = a_r + u*64;
            float4 v = *(const float4*)(Ab + (size_t)r * K + (k0 + a_c));
            As[a_c+0][r] = v.x; As[a_c+1][r] = v.y;
            As[a_c+2][r] = v.z; As[a_c+3][r] = v.w;
        }
        #pragma unroll
        for (int u = 0; u < 2; u++) {
            int r = b_r + u*8;
            int col = bx*128 + b_c;
            float4 v = make_float4(0.f, 0.f, 0.f, 0.f);
            if (col < N) v = *(const float4*)(W + (size_t)(k0 + r) * N + col);
            *(float4*)&Bs[r][b_c] = v;
        }
        __syncthreads();
        #pragma unroll
        for (int k = 0; k < 16; k++) {
            float a[8], b[8];
            *(float4*)&a[0] = *(const float4*)&As[k][ty*8];
            *(float4*)&a[4] = *(const float4*)&As[k][ty*8+4];
            *(float4*)&b[0] = *(const float4*)&Bs[k][tx*8];
            *(float4*)&b[4] = *(const float4*)&Bs[k][tx*8+4];
            #pragma unroll
            for (int i = 0; i < 8; i++)
                #pragma unroll
                for (int j = 0; j < 8; j++)
                    acc[i][j] = fmaf(a[i], b[j], acc[i][j]);
        }
        __syncthreads();
    }

    const int row0 = by*128 + ty*8;
    const int col0 = bx*128 + tx*8;
    #pragma unroll
    for (int i = 0; i < 8; i++) {
        #pragma unroll
        for (int j = 0; j < 8; j += 4) {
            int col = col0 + j;
            if (col < N) {
                float4 v = make_float4(acc[i][j], acc[i][j+1], acc[i][j+2], acc[i][j+3]);
                if (BIAS) {
                    v.x += bias[col+0]; v.y += bias[col+1];
                    v.z += bias[col+2]; v.w += bias[col+3];
                }
                *(float4*)(C + (size_t)(row0+i)*N + col) = v;
            }
        }
    }
}

// ---------------- RoPE + head-concat pack kernels ----------------
// Q[row, h*128 + d] = d<64 ? q_c[row, h*64+d] : rope(q_r[row, h*64 + (d-64)])
__device__ __forceinline__ float rope_apply(const float* v32, int dd, int pos)
{
    int fi = dd & 31;
    float inv = powf(10000.f, -(float)(2*fi) / 64.f);
    float ang = (float)pos * inv;
    float cs = cosf(ang), sn = sinf(ang);
    float v = v32[dd];
    float w = (dd < 32) ? -v32[dd + 32] : v32[dd - 32];
    return v * cs + w * sn;
}

__global__ void pack_q_kernel()
{
    int idx = blockIdx.x * blockDim.x + threadIdx.x;   // over NM*NHID
    int row = idx >> 11;
    int c   = idx & (NHID - 1);
    int h = c >> 7, d = c & 127;
    float out;
    if (d < 64) {
        out = g_qc[(size_t)row*1024 + h*64 + d];
    } else {
        const float* qr = g_qr + (size_t)row*1024 + h*64;
        out = rope_apply(qr, d - 64, row & (NS - 1));
    }
    g_Q[idx] = out;
}

__global__ void pack_k_kernel()
{
    int idx = blockIdx.x * blockDim.x + threadIdx.x;
    int row = idx >> 11;
    int c   = idx & (NHID - 1);
    int h = c >> 7, d = c & 127;
    float out;
    if (d < 64) {
        out = g_kc[(size_t)row*1024 + h*64 + d];
    } else {
        const float* kr = g_krr + (size_t)row*NRD;     // shared rope head
        out = rope_apply(kr, d - 64, row & (NS - 1));
    }
    g_K[idx] = out;
}

// ---------------- causal flash attention (fp32, Br=Bc=64, D=128) ----------------
// grid: (S/64, H, B), 256 threads. Q/K/V/O layout: [B, S, H, 128] (row stride 2048).
// smem: Qs 64x129, Ks 64x129, Vs 64x132, Ps 64x65 -> 116,480 B dynamic.
__global__ void __launch_bounds__(256)
flash_kernel(const float* __restrict__ Q, const float* __restrict__ K,
             const float* __restrict__ V, float* __restrict__ O)
{
    extern __shared__ float sm[];
    float* Qs = sm;                       // 64*129 = 8256
    float* Ks = sm + 64*129;              // 64*129
    float* Vs = sm + 2*64*129;            // 64*132 (float4-aligned stride)
    float* Ps = Vs + 64*132;              // 64*65

    const int tid = threadIdx.x;
    const int tx = tid & 15, ty = tid >> 4;
    const int h = blockIdx.y, b = blockIdx.z;
    const int q0 = blockIdx.x * 64;
    const size_t base = ((size_t)b * NS) * NHID + (size_t)h * NHD;

    // load Q tile
    for (int i = tid; i < 64*32; i += 256) {
        int r = i >> 5, c4 = (i & 31) << 2;
        float4 v = *(const float4*)(Q + base + (size_t)(q0 + r) * NHID + c4);
        Qs[r*129 + c4+0] = v.x; Qs[r*129 + c4+1] = v.y;
        Qs[r*129 + c4+2] = v.z; Qs[r*129 + c4+3] = v.w;
    }

    float m[4], l[4], o[4][8];
    #pragma unroll
    for (int i = 0; i < 4; i++) {
        m[i] = -INFINITY; l[i] = 0.f;
        #pragma unroll
        for (int j = 0; j < 8; j++) o[i][j] = 0.f;
    }
    const float scale = 0.08838834764831845f;  // 1/sqrt(128)
    const int ntiles = blockIdx.x + 1;          // causal: kv tiles 0..bx

    for (int t = 0; t < ntiles; t++) {
        const int k0 = t * 64;
        __syncthreads();   // protect Ks/Vs/Ps from previous iteration's readers
        for (int i = tid; i < 64*32; i += 256) {
            int r = i >> 5, c4 = (i & 31) << 2;
            float4 kv = *(const float4*)(K + base + (size_t)(k0 + r) * NHID + c4);
            Ks[r*129 + c4+0] = kv.x; Ks[r*129 + c4+1] = kv.y;
            Ks[r*129 + c4+2] = kv.z; Ks[r*129 + c4+3] = kv.w;
            float4 vv = *(const float4*)(V + base + (size_t)(k0 + r) * NHID + c4);
            *(float4*)&Vs[r*132 + c4] = vv;
        }
        __syncthreads();

        // S = Q @ K^T  (64x64, each thread 4x4)
        float acc[4][4];
        #pragma unroll
        for (int i = 0; i < 4; i++)
            #pragma unroll
            for (int j = 0; j < 4; j++) acc[i][j] = 0.f;

        for (int k = 0; k < 128; k++) {
            float a[4], bb[4];
            #pragma unroll
            for (int i = 0; i < 4; i++) a[i]  = Qs[(ty*4+i)*129 + k];
            #pragma unroll
            for (int j = 0; j < 4; j++) bb[j] = Ks[(tx*4+j)*129 + k];
            #pragma unroll
            for (int i = 0; i < 4; i++)
                #pragma unroll
                for (int j = 0; j < 4; j++)
                    acc[i][j] = fmaf(a[i], bb[j], acc[i][j]);
        }

        const bool diag = (t == blockIdx.x);
        float mt[4];
        #pragma unroll
        for (int i = 0; i < 4; i++) {
            mt[i] = -INFINITY;
            #pragma unroll
            for (int j = 0; j < 4; j++) {
                float s = acc[i][j] * scale;
                if (diag && (k0 + tx*4 + j) > (q0 + ty*4 + i)) s = -INFINITY;
                acc[i][j] = s;
                mt[i] = fmaxf(mt[i], s);
            }
        }
        // row-max across the 16 threads of each thread-row (lanes 0-15 / 16-31)
        #pragma unroll
        for (int off = 1; off < 16; off <<= 1)
            #pragma unroll
            for (int i = 0; i < 4; i++)
                mt[i] = fmaxf(mt[i], __shfl_xor_sync(0xffffffffu, mt[i], off));

        float corr[4], ls[4];
        #pragma unroll
        for (int i = 0; i < 4; i++) {
            float mn = fmaxf(m[i], mt[i]);
            corr[i] = expf(m[i] - mn);
            m[i] = mn;
            ls[i] = 0.f;
            #pragma unroll
            for (int j = 0; j < 4; j++) {
                float p = expf(acc[i][j] - mn);
                Ps[(ty*4+i)*65 + tx*4 + j] = p;
                ls[i] += p;
            }
        }
        #pragma unroll
        for (int off = 1; off < 16; off <<= 1)
            #pragma unroll
            for (int i = 0; i < 4; i++)
                ls[i] += __shfl_xor_sync(0xffffffffu, ls[i], off);
        #pragma unroll
        for (int i = 0; i < 4; i++) {
            l[i] = l[i] * corr[i] + ls[i];
            #pragma unroll
            for (int j = 0; j < 8; j++) o[i][j] *= corr[i];
        }
        __syncthreads();   // Ps visible

        // O += P @ V  (64x128, each thread 4 rows x 8 cols)
        for (int k = 0; k < 64; k++) {
            float4 v0 = *(const float4*)&Vs[k*132 + tx*8];
            float4 v1 = *(const float4*)&Vs[k*132 + tx*8 + 4];
            #pragma unroll
            for (int i = 0; i < 4; i++) {
                float p = Ps[(ty*4+i)*65 + k];
                o[i][0] = fmaf(p, v0.x, o[i][0]);
                o[i][1] = fmaf(p, v0.y, o[i][1]);
                o[i][2] = fmaf(p, v0.z, o[i][2]);
                o[i][3] = fmaf(p, v0.w, o[i][3]);
                o[i][4] = fmaf(p, v1.x, o[i][4]);
                o[i][5] = fmaf(p, v1.y, o[i][5]);
                o[i][6] = fmaf(p, v1.z, o[i][6]);
                o[i][7] = fmaf(p, v1.w, o[i][7]);
            }
        }
    }

    // epilogue: normalize and store ctx
    #pragma unroll
    for (int i = 0; i < 4; i++) {
        float inv = 1.f / l[i];
        int row = q0 + ty*4 + i;
        float4 w0 = make_float4(o[i][0]*inv, o[i][1]*inv, o[i][2]*inv, o[i][3]*inv);
        float4 w1 = make_float4(o[i][4]*inv, o[i][5]*inv, o[i][6]*inv, o[i][7]*inv);
        *(float4*)(O + base + (size_t)row * NHID + tx*8)     = w0;
        *(float4*)(O + base + (size_t)row * NHID + tx*8 + 4) = w1;
    }
}

// ---------------- host launcher ----------------
extern "C" void kernel_launch(void* const* d_in, const int* in_sizes, int n_in,
                              void* d_out, int out_size)
{
    const float* x        = (const float*)d_in[0];
    const float* wq_down  = (const float*)d_in[1];
    const float* wq_up    = (const float*)d_in[2];
    const float* wq_rope  = (const float*)d_in[3];
    const float* wk_rope  = (const float*)d_in[4];
    const float* wkv_down = (const float*)d_in[5];
    const float* wk_up    = (const float*)d_in[6];
    const float* wv_up    = (const float*)d_in[7];
    const float* wo       = (const float*)d_in[8];
    const float* bo       = (const float*)d_in[9];
    float* out = (float*)d_out;

    float *qlat, *kvlat, *krr, *qc, *qr, *kc, *V, *Q, *K, *ctx;
    cudaGetSymbolAddress((void**)&qlat,  g_qlat);
    cudaGetSymbolAddress((void**)&kvlat, g_kvlat);
    cudaGetSymbolAddress((void**)&krr,   g_krr);
    cudaGetSymbolAddress((void**)&qc,    g_qc);
    cudaGetSymbolAddress((void**)&qr,    g_qr);
    cudaGetSymbolAddress((void**)&kc,    g_kc);
    cudaGetSymbolAddress((void**)&V,     g_V);
    cudaGetSymbolAddress((void**)&Q,     g_Q);
    cudaGetSymbolAddress((void**)&K,     g_K);
    cudaGetSymbolAddress((void**)&ctx,   g_ctx);

    dim3 thr(256);

    // projections
    sgemm_kernel<false><<<dim3(4, 64), thr>>>(x,     wq_down,  qlat, nullptr,  512, 2048);
    sgemm_kernel<false><<<dim3(4, 64), thr>>>(x,     wkv_down, kvlat, nullptr, 512, 2048);
    sgemm_kernel<false><<<dim3(1, 64), thr>>>(x,     wk_rope,  krr,  nullptr,   64, 2048);
    sgemm_kernel<false><<<dim3(8, 64), thr>>>(qlat,  wq_up,    qc,   nullptr, 1024,  512);
    sgemm_kernel<false><<<dim3(8, 64), thr>>>(qlat,  wq_rope,  qr,   nullptr, 1024,  512);
    sgemm_kernel<false><<<dim3(8, 64), thr>>>(kvlat, wk_up,    kc,   nullptr, 1024,  512);
    sgemm_kernel<false><<<dim3(16,64), thr>>>(kvlat, wv_up,    V,    nullptr, 2048,  512);

    // RoPE + concat into attention layout
    pack_q_kernel<<<(NM*NHID)/256, thr>>>();
    pack_k_kernel<<<(NM*NHID)/256, thr>>>();

    // fused causal flash attention
    size_t smem = (size_t)(2*64*129 + 64*132 + 64*65) * sizeof(float);  // 116480 B
    cudaFuncSetAttribute(flash_kernel, cudaFuncAttributeMaxDynamicSharedMemorySize, (int)smem);
    flash_kernel<<<dim3(NS/64, NH, NB), thr, smem>>>(Q, K, V, ctx);

    // output projection + bias
    sgemm_kernel<true><<<dim3(16,64), thr>>>(ctx, wo, out, bo, 2048, 2048);
}

// round 2
// speedup vs baseline: 1.4168x; 1.4168x over previous
#include <cuda_runtime.h>
#include <cuda_bf16.h>
#include <math.h>
#include <stdint.h>

using bf16 = __nv_bfloat16;

// ---------------- problem constants ----------------
#define NB   4
#define NS   2048
#define NH   16
#define NHD  128
#define NRD  64
#define NLAT 512
#define NHID 2048
#define NM   (NB*NS)        // 8192 rows total

// ---------------- device scratch (static, allocation-free) ----------------
__device__ float g_qlat [(size_t)NM*NLAT];
__device__ float g_kvlat[(size_t)NM*NLAT];
__device__ float g_krr  [(size_t)NM*NRD];
__device__ float g_qc   [(size_t)NM*1024];
__device__ float g_qr   [(size_t)NM*1024];
__device__ float g_kc   [(size_t)NM*1024];
__device__ float g_V    [(size_t)NM*NHID];
__device__ float g_Q    [(size_t)NM*NHID];
__device__ float g_K    [(size_t)NM*NHID];
__device__ float g_ctx  [(size_t)NM*NHID];

// bf16 hi/lo split buffers
__device__ bf16 g_xs   [2][(size_t)NM*NHID];
__device__ bf16 g_wqd_s[2][2048*512];
__device__ bf16 g_wkvd_s[2][2048*512];
__device__ bf16 g_wqu_s[2][512*1024];
__device__ bf16 g_wqr_s[2][512*1024];
__device__ bf16 g_wku_s[2][512*1024];
__device__ bf16 g_wvu_s[2][512*2048];
__device__ bf16 g_wo_s [2][2048*2048];
__device__ bf16 g_qlat_s[2][(size_t)NM*NLAT];
__device__ bf16 g_kvlat_s[2][(size_t)NM*NLAT];
__device__ bf16 g_ctx_s[2][(size_t)NM*NHID];

// ---------------- fp32 -> (bf16 hi, bf16 lo) split ----------------
__global__ void split_kernel(const float* __restrict__ in,
                             bf16* __restrict__ hi, bf16* __restrict__ lo)
{
    size_t i = (size_t)blockIdx.x * blockDim.x + threadIdx.x;
    float f = in[i];
    bf16 h = __float2bfloat16(f);
    hi[i] = h;
    lo[i] = __float2bfloat16(f - __bfloat162float(h));
}

// ---------------- tensor-core split-bf16 GEMM ----------------
// C[M,N] = A[M,K] @ W[K,N] (+bias), fp32-quality via 3-term bf16 split.
// Block 128x128, BK=32, 256 threads (8 warps, 2x4), warp tile 64x32.
#define SA_ELEMS (128*40)   // padded A tile per version
#define SB_ELEMS (32*136)   // padded B tile per version
#define SMEM_BYTES ((4*SA_ELEMS + 4*SB_ELEMS)*2)   // 75776

__device__ __forceinline__ void cp16(uint32_t s, const void* g) {
    asm volatile("cp.async.cg.shared.global [%0], [%1], 16;\n" :: "r"(s), "l"(g));
}

#define LDM_X4(R, addr) \
    asm volatile("ldmatrix.sync.aligned.m8n8.x4.shared.b16 {%0,%1,%2,%3}, [%4];" \
        : "=r"(R[0]), "=r"(R[1]), "=r"(R[2]), "=r"(R[3]) : "r"(addr))

#define LDM_X4_T(R, addr) \
    asm volatile("ldmatrix.sync.aligned.m8n8.x4.trans.shared.b16 {%0,%1,%2,%3}, [%4];" \
        : "=r"(R[0]), "=r"(R[1]), "=r"(R[2]), "=r"(R[3]) : "r"(addr))

#define MMA16816(D, A, B0, B1) \
    asm volatile("mma.sync.aligned.m16n8k16.row.col.f32.bf16.bf16.f32 " \
        "{%0,%1,%2,%3}, {%4,%5,%6,%7}, {%8,%9}, {%0,%1,%2,%3};" \
        : "+f"(D[0]), "+f"(D[1]), "+f"(D[2]), "+f"(D[3]) \
        : "r"(A[0]), "r"(A[1]), "r"(A[2]), "r"(A[3]), "r"(B0), "r"(B1))

__device__ __forceinline__ void bgemm_fill(
    uint32_t smem_base, int buf,
    const bf16* __restrict__ Ah, const bf16* __restrict__ Al,
    const bf16* __restrict__ Bh, const bf16* __restrict__ Bl,
    int tid, int row0, int col0, int k0, int N, int K)
{
    #pragma unroll
    for (int c = 0; c < 2; c++) {
        int chunk = tid + 256*c;
        int r = chunk >> 2, cc = chunk & 3;           // 128 rows x 4 x 16B
        size_t goff = (size_t)(row0 + r) * K + k0 + cc*8;
        uint32_t so = smem_base + (uint32_t)((buf*2+0)*SA_ELEMS + r*40 + cc*8)*2;
        cp16(so, Ah + goff);
        so = smem_base + (uint32_t)((buf*2+1)*SA_ELEMS + r*40 + cc*8)*2;
        cp16(so, Al + goff);
    }
    #pragma unroll
    for (int c = 0; c < 2; c++) {
        int chunk = tid + 256*c;
        int r = chunk >> 4, cc = chunk & 15;          // 32 rows x 16 x 16B
        size_t goff = (size_t)(k0 + r) * N + col0 + cc*8;
        uint32_t so = smem_base + (uint32_t)(4*SA_ELEMS + (buf*2+0)*SB_ELEMS + r*136 + cc*8)*2;
        cp16(so, Bh + goff);
        so = smem_base + (uint32_t)(4*SA_ELEMS + (buf*2+1)*SB_ELEMS + r*136 + cc*8)*2;
        cp16(so, Bl + goff);
    }
    asm volatile("cp.async.commit_group;");
}

template<bool BIAS>
__global__ void __launch_bounds__(256, 1)
bgemm_kernel(const bf16* __restrict__ Ah, const bf16* __restrict__ Al,
             const bf16* __restrict__ Bh, const bf16* __restrict__ Bl,
             float* __restrict__ C, const float* __restrict__ bias,
             int N, int K)
{
    extern __shared__ bf16 smem_dyn[];
    const uint32_t smem_base = (uint32_t)__cvta_generic_to_shared(smem_dyn);

    const int tid  = threadIdx.x;
    const int lane = tid & 31;
    const int wid  = tid >> 5;
    const int m0w  = (wid >> 2) * 64;
    const int n0w  = (wid & 3) * 32;
    const int row0 = blockIdx.y * 128;
    const int col0 = blockIdx.x * 128;

    float acc[4][4][4];
    #pragma unroll
    for (int i = 0; i < 4; i++)
        #pragma unroll
        for (int j = 0; j < 4; j++)
            #pragma unroll
            for (int k = 0; k < 4; k++) acc[i][j][k] = 0.f;

    const int niter = K >> 5;
    bgemm_fill(smem_base, 0, Ah, Al, Bh, Bl, tid, row0, col0, 0, N, K);

    const int aRow  = m0w + (lane & 15);
    const int aCol8 = 8 * (lane >> 4);
    const int bRow  = lane & 15;
    const int bCol8 = n0w + 8 * (lane >> 4);

    for (int it = 0; it < niter; ++it) {
        const int buf = it & 1;
        if (it + 1 < niter) {
            bgemm_fill(smem_base, buf ^ 1, Ah, Al, Bh, Bl, tid, row0, col0, (it+1)*32, N, K);
            asm volatile("cp.async.wait_group 1;");
        } else {
            asm volatile("cp.async.wait_group 0;");
        }
        __syncthreads();

        #pragma unroll
        for (int sub = 0; sub < 32; sub += 16) {
            uint32_t ah[4][4], al[4][4];
            #pragma unroll
            for (int mt = 0; mt < 4; mt++) {
                uint32_t addr = smem_base +
                    (uint32_t)((buf*2)*SA_ELEMS + (aRow + mt*16)*40 + sub + aCol8)*2;
                LDM_X4(ah[mt], addr);
                addr += SA_ELEMS*2;
                LDM_X4(al[mt], addr);
            }
            uint32_t bh[2][4], bl[2][4];
            #pragma unroll
            for (int np = 0; np < 2; np++) {
                uint32_t addr = smem_base +
                    (uint32_t)(4*SA_ELEMS + (buf*2)*SB_ELEMS + (sub + bRow)*136 + bCol8 + np*16)*2;
                LDM_X4_T(bh[np], addr);
                addr += SB_ELEMS*2;
                LDM_X4_T(bl[np], addr);
            }
            #pragma unroll
            for (int mt = 0; mt < 4; mt++)
                #pragma unroll
                for (int nt = 0; nt < 4; nt++) {
                    uint32_t b0h = bh[nt>>1][(nt&1)*2], b1h = bh[nt>>1][(nt&1)*2+1];
                    uint32_t b0l = bl[nt>>1][(nt&1)*2], b1l = bl[nt>>1][(nt&1)*2+1];
                    MMA16816(acc[mt][nt], ah[mt], b0h, b1h);   // hi*hi
                    MMA16816(acc[mt][nt], ah[mt], b0l, b1l);   // hi*lo
                    MMA16816(acc[mt][nt], al[mt], b0h, b1h);   // lo*hi
                }
        }
        __syncthreads();
    }

    // epilogue
    #pragma unroll
    for (int mt = 0; mt < 4; mt++) {
        #pragma unroll
        for (int nt = 0; nt < 4; nt++) {
            int r  = row0 + m0w + mt*16 + (lane >> 2);
            int cc = col0 + n0w + nt*8 + (lane & 3)*2;
            float b0 = 0.f, b1 = 0.f;
            if (BIAS) { b0 = bias[cc]; b1 = bias[cc+1]; }
            float2 v0 = make_float2(acc[mt][nt][0] + b0, acc[mt][nt][1] + b1);
            float2 v1 = make_float2(acc[mt][nt][2] + b0, acc[mt][nt][3] + b1);
            *(float2*)(C + (size_t)r     * N + cc) = v0;
            *(float2*)(C + (size_t)(r+8) * N + cc) = v1;
        }
    }
}

// ---------------- fp32 SGEMM (kept for tiny wk_rope, N=64) ----------------
template<bool BIAS>
__global__ void __launch_bounds__(256)
sgemm_kernel(const float* __restrict__ A, const float* __restrict__ W,
             float* __restrict__ C, const float* __restrict__ bias,
             int N, int K)
{
    __shared__ float As[16][132];
    __shared__ float Bs[16][128];

    const int tid = threadIdx.x;
    const int tx = tid & 15, ty = tid >> 4;
    const int bx = blockIdx.x, by = blockIdx.y;

    const int a_r = tid >> 2;
    const int a_c = (tid & 3) << 2;
    const int b_r = tid >> 5;
    const int b_c = (tid & 31) << 2;

    const float* Ab = A + (size_t)by * 128 * K;

    float acc[8][8];
    #pragma unroll
    for (int i = 0; i < 8; i++)
        #pragma unroll
        for (int j = 0; j < 8; j++) acc[i][j] = 0.f;

    for (int k0 = 0; k0 < K; k0 += 16) {
        #pragma unroll
        for (int u = 0; u < 2; u++) {
            int r = a_r + u*64;
            float4 v = *(const float4*)(Ab + (size_t)r * K + (k0 + a_c));
            As[a_c+0][r] = v.x; As[a_c+1][r] = v.y;
            As[a_c+2][r] = v.z; As[a_c+3][r] = v.w;
        }
        #pragma unroll
        for (int u = 0; u < 2; u++) {
            int r = b_r + u*8;
            int col = bx*128 + b_c;
            float4 v = make_float4(0.f, 0.f, 0.f, 0.f);
            if (col < N) v = *(const float4*)(W + (size_t)(k0 + r) * N + col);
            *(float4*)&Bs[r][b_c] = v;
        }
        __syncthreads();
        #pragma unroll
        for (int k = 0; k < 16; k++) {
            float a[8], b[8];
            *(float4*)&a[0] = *(const float4*)&As[k][ty*8];
            *(float4*)&a[4] = *(const float4*)&As[k][ty*8+4];
            *(float4*)&b[0] = *(const float4*)&Bs[k][tx*8];
            *(float4*)&b[4] = *(const float4*)&Bs[k][tx*8+4];
            #pragma unroll
            for (int i = 0; i < 8; i++)
                #pragma unroll
                for (int j = 0; j < 8; j++)
                    acc[i][j] = fmaf(a[i], b[j], acc[i][j]);
        }
        __syncthreads();
    }

    const int row0 = by*128 + ty*8;
    const int col0 = bx*128 + tx*8;
    #pragma unroll
    for (int i = 0; i < 8; i++) {
        #pragma unroll
        for (int j = 0; j < 8; j += 4) {
            int col = col0 + j;
            if (col < N) {
                float4 v = make_float4(acc[i][j], acc[i][j+1], acc[i][j+2], acc[i][j+3]);
                if (BIAS) {
                    v.x += bias[col+0]; v.y += bias[col+1];
                    v.z += bias[col+2]; v.w += bias[col+3];
                }
                *(float4*)(C + (size_t)(row0+i)*N + col) = v;
            }
        }
    }
}

// ---------------- RoPE + head-concat pack kernels ----------------
__device__ __forceinline__ float rope_apply(const float* v32, int dd, int pos)
{
    int fi = dd & 31;
    float inv = powf(10000.f, -(float)(2*fi) / 64.f);
    float ang = (float)pos * inv;
    float cs = cosf(ang), sn = sinf(ang);
    float v = v32[dd];
    float w = (dd < 32) ? -v32[dd + 32] : v32[dd - 32];
    return v * cs + w * sn;
}

__global__ void pack_q_kernel()
{
    int idx = blockIdx.x * blockDim.x + threadIdx.x;
    int row = idx >> 11;
    int c   = idx & (NHID - 1);
    int h = c >> 7, d = c & 127;
    float out;
    if (d < 64) {
        out = g_qc[(size_t)row*1024 + h*64 + d];
    } else {
        const float* qr = g_qr + (size_t)row*1024 + h*64;
        out = rope_apply(qr, d - 64, row & (NS - 1));
    }
    g_Q[idx] = out;
}

__global__ void pack_k_kernel()
{
    int idx = blockIdx.x * blockDim.x + threadIdx.x;
    int row = idx >> 11;
    int c   = idx & (NHID - 1);
    int h = c >> 7, d = c & 127;
    float out;
    if (d < 64) {
        out = g_kc[(size_t)row*1024 + h*64 + d];
    } else {
        const float* kr = g_krr + (size_t)row*NRD;
        out = rope_apply(kr, d - 64, row & (NS - 1));
    }
    g_K[idx] = out;
}

// ---------------- causal flash attention (fp32, Br=Bc=64, D=128) ----------------
__global__ void __launch_bounds__(256)
flash_kernel(const float* __restrict__ Q, const float* __restrict__ K,
             const float* __restrict__ V, float* __restrict__ O)
{
    extern __shared__ float sm[];
    float* Qs = sm;
    float* Ks = sm + 64*129;
    float* Vs = sm + 2*64*129;
    float* Ps = Vs + 64*132;

    const int tid = threadIdx.x;
    const int tx = tid & 15, ty = tid >> 4;
    const int h = blockIdx.y, b = blockIdx.z;
    const int q0 = blockIdx.x * 64;
    const size_t base = ((size_t)b * NS) * NHID + (size_t)h * NHD;

    for (int i = tid; i < 64*32; i += 256) {
        int r = i >> 5, c4 = (i & 31) << 2;
        float4 v = *(const float4*)(Q + base + (size_t)(q0 + r) * NHID + c4);
        Qs[r*129 + c4+0] = v.x; Qs[r*129 + c4+1] = v.y;
        Qs[r*129 + c4+2] = v.z; Qs[r*129 + c4+3] = v.w;
    }

    float m[4], l[4], o[4][8];
    #pragma unroll
    for (int i = 0; i < 4; i++) {
        m[i] = -INFINITY; l[i] = 0.f;
        #pragma unroll
        for (int j = 0; j < 8; j++) o[i][j] = 0.f;
    }
    const float scale = 0.08838834764831845f;
    const int ntiles = blockIdx.x + 1;

    for (int t = 0; t < ntiles; t++) {
        const int k0 = t * 64;
        __syncthreads();
        for (int i = tid; i < 64*32; i += 256) {
            int r = i >> 5, c4 = (i & 31) << 2;
            float4 kv = *(const float4*)(K + base + (size_t)(k0 + r) * NHID + c4);
            Ks[r*129 + c4+0] = kv.x; Ks[r*129 + c4+1] = kv.y;
            Ks[r*129 + c4+2] = kv.z; Ks[r*129 + c4+3] = kv.w;
            float4 vv = *(const float4*)(V + base + (size_t)(k0 + r) * NHID + c4);
            *(float4*)&Vs[r*132 + c4] = vv;
        }
        __syncthreads();

        float acc[4][4];
        #pragma unroll
        for (int i = 0; i < 4; i++)
            #pragma unroll
            for (int j = 0; j < 4; j++) acc[i][j] = 0.f;

        for (int k = 0; k < 128; k++) {
            float a[4], bb[4];
            #pragma unroll
            for (int i = 0; i < 4; i++) a[i]  = Qs[(ty*4+i)*129 + k];
            #pragma unroll
            for (int j = 0; j < 4; j++) bb[j] = Ks[(tx*4+j)*129 + k];
            #pragma unroll
            for (int i = 0; i < 4; i++)
                #pragma unroll
                for (int j = 0; j < 4; j++)
                    acc[i][j] = fmaf(a[i], bb[j], acc[i][j]);
        }

        const bool diag = (t == blockIdx.x);
        float mt[4];
        #pragma unroll
        for (int i = 0; i < 4; i++) {
            mt[i] = -INFINITY;
            #pragma unroll
            for (int j = 0; j < 4; j++) {
                float s = acc[i][j] * scale;
                if (diag && (k0 + tx*4 + j) > (q0 + ty*4 + i)) s = -INFINITY;
                acc[i][j] = s;
                mt[i] = fmaxf(mt[i], s);
            }
        }
        #pragma unroll
        for (int off = 1; off < 16; off <<= 1)
            #pragma unroll
            for (int i = 0; i < 4; i++)
                mt[i] = fmaxf(mt[i], __shfl_xor_sync(0xffffffffu, mt[i], off));

        float corr[4], ls[4];
        #pragma unroll
        for (int i = 0; i < 4; i++) {
            float mn = fmaxf(m[i], mt[i]);
            corr[i] = expf(m[i] - mn);
            m[i] = mn;
            ls[i] = 0.f;
            #pragma unroll
            for (int j = 0; j < 4; j++) {
                float p = expf(acc[i][j] - mn);
                Ps[(ty*4+i)*65 + tx*4 + j] = p;
                ls[i] += p;
            }
        }
        #pragma unroll
        for (int off = 1; off < 16; off <<= 1)
            #pragma unroll
            for (int i = 0; i < 4; i++)
                ls[i] += __shfl_xor_sync(0xffffffffu, ls[i], off);
        #pragma unroll
        for (int i = 0; i < 4; i++) {
            l[i] = l[i] * corr[i] + ls[i];
            #pragma unroll
            for (int j = 0; j < 8; j++) o[i][j] *= corr[i];
        }
        __syncthreads();

        for (int k = 0; k < 64; k++) {
            float4 v0 = *(const float4*)&Vs[k*132 + tx*8];
            float4 v1 = *(const float4*)&Vs[k*132 + tx*8 + 4];
            #pragma unroll
            for (int i = 0; i < 4; i++) {
                float p = Ps[(ty*4+i)*65 + k];
                o[i][0] = fmaf(p, v0.x, o[i][0]);
                o[i][1] = fmaf(p, v0.y, o[i][1]);
                o[i][2] = fmaf(p, v0.z, o[i][2]);
                o[i][3] = fmaf(p, v0.w, o[i][3]);
                o[i][4] = fmaf(p, v1.x, o[i][4]);
                o[i][5] = fmaf(p, v1.y, o[i][5]);
                o[i][6] = fmaf(p, v1.z, o[i][6]);
                o[i][7] = fmaf(p, v1.w, o[i][7]);
            }
        }
    }

    #pragma unroll
    for (int i = 0; i < 4; i++) {
        float inv = 1.f / l[i];
        int row = q0 + ty*4 + i;
        float4 w0 = make_float4(o[i][0]*inv, o[i][1]*inv, o[i][2]*inv, o[i][3]*inv);
        float4 w1 = make_float4(o[i][4]*inv, o[i][5]*inv, o[i][6]*inv, o[i][7]*inv);
        *(float4*)(O + base + (size_t)row * NHID + tx*8)     = w0;
        *(float4*)(O + base + (size_t)row * NHID + tx*8 + 4) = w1;
    }
}

// ---------------- host launcher ----------------
static inline void run_split(const float* src, bf16* hi, bf16* lo, size_t n)
{
    split_kernel<<<(unsigned)(n / 256), 256>>>(src, hi, lo);
}

extern "C" void kernel_launch(void* const* d_in, const int* in_sizes, int n_in,
                              void* d_out, int out_size)
{
    const float* x        = (const float*)d_in[0];
    const float* wq_down  = (const float*)d_in[1];
    const float* wq_up    = (const float*)d_in[2];
    const float* wq_rope  = (const float*)d_in[3];
    const float* wk_rope  = (const float*)d_in[4];
    const float* wkv_down = (const float*)d_in[5];
    const float* wk_up    = (const float*)d_in[6];
    const float* wv_up    = (const float*)d_in[7];
    const float* wo       = (const float*)d_in[8];
    const float* bo       = (const float*)d_in[9];
    float* out = (float*)d_out;

    float *qlat, *kvlat, *krr, *qc, *qr, *kc, *V, *Q, *K, *ctx;
    cudaGetSymbolAddress((void**)&qlat,  g_qlat);
    cudaGetSymbolAddress((void**)&kvlat, g_kvlat);
    cudaGetSymbolAddress((void**)&krr,   g_krr);
    cudaGetSymbolAddress((void**)&qc,    g_qc);
    cudaGetSymbolAddress((void**)&qr,    g_qr);
    cudaGetSymbolAddress((void**)&kc,    g_kc);
    cudaGetSymbolAddress((void**)&V,     g_V);
    cudaGetSymbolAddress((void**)&Q,     g_Q);
    cudaGetSymbolAddress((void**)&K,     g_K);
    cudaGetSymbolAddress((void**)&ctx,   g_ctx);

    bf16 *xs, *wqd, *wkvd, *wqu, *wqr, *wku, *wvu, *wos, *qls, *kvls, *ctxs;
    cudaGetSymbolAddress((void**)&xs,   g_xs);
    cudaGetSymbolAddress((void**)&wqd,  g_wqd_s);
    cudaGetSymbolAddress((void**)&wkvd, g_wkvd_s);
    cudaGetSymbolAddress((void**)&wqu,  g_wqu_s);
    cudaGetSymbolAddress((void**)&wqr,  g_wqr_s);
    cudaGetSymbolAddress((void**)&wku,  g_wku_s);
    cudaGetSymbolAddress((void**)&wvu,  g_wvu_s);
    cudaGetSymbolAddress((void**)&wos,  g_wo_s);
    cudaGetSymbolAddress((void**)&qls,  g_qlat_s);
    cudaGetSymbolAddress((void**)&kvls, g_kvlat_s);
    cudaGetSymbolAddress((void**)&ctxs, g_ctx_s);

    const size_t XN   = (size_t)NM*NHID;
    const size_t WD   = 2048*512;
    const size_t WU   = 512*1024;
    const size_t WV   = 512*2048;
    const size_t WO   = 2048*2048;
    const size_t QLN  = (size_t)NM*NLAT;

    cudaFuncSetAttribute(bgemm_kernel<false>, cudaFuncAttributeMaxDynamicSharedMemorySize, SMEM_BYTES);
    cudaFuncSetAttribute(bgemm_kernel<true>,  cudaFuncAttributeMaxDynamicSharedMemorySize, SMEM_BYTES);

    dim3 thr(256);

    // splits: x + weights
    run_split(x,        xs,        xs + XN,    XN);
    run_split(wq_down,  wqd,       wqd + WD,   WD);
    run_split(wkv_down, wkvd,      wkvd + WD,  WD);
    run_split(wq_up,    wqu,       wqu + WU,   WU);
    run_split(wq_rope,  wqr,       wqr + WU,   WU);
    run_split(wk_up,    wku,       wku + WU,   WU);
    run_split(wv_up,    wvu,       wvu + WV,   WV);
    run_split(wo,       wos,       wos + WO,   WO);

    // down projections (tensor cores)
    bgemm_kernel<false><<<dim3(4, 64), thr, SMEM_BYTES>>>(xs, xs + XN, wqd,  wqd + WD,  qlat,  nullptr, 512, 2048);
    bgemm_kernel<false><<<dim3(4, 64), thr, SMEM_BYTES>>>(xs, xs + XN, wkvd, wkvd + WD, kvlat, nullptr, 512, 2048);
    // tiny rope-key projection (fp32 path, N=64)
    sgemm_kernel<false><<<dim3(1, 64), thr>>>(x, wk_rope, krr, nullptr, 64, 2048);

    // split latents
    run_split(qlat,  qls,  qls + QLN,  QLN);
    run_split(kvlat, kvls, kvls + QLN, QLN);

    // up projections (tensor cores)
    bgemm_kernel<false><<<dim3(8, 64),  thr, SMEM_BYTES>>>(qls,  qls + QLN,  wqu, wqu + WU, qc, nullptr, 1024, 512);
    bgemm_kernel<false><<<dim3(8, 64),  thr, SMEM_BYTES>>>(qls,  qls + QLN,  wqr, wqr + WU, qr, nullptr, 1024, 512);
    bgemm_kernel<false><<<dim3(8, 64),  thr, SMEM_BYTES>>>(kvls, kvls + QLN, wku, wku + WU, kc, nullptr, 1024, 512);
    bgemm_kernel<false><<<dim3(16, 64), thr, SMEM_BYTES>>>(kvls, kvls + QLN, wvu, wvu + WV, V,  nullptr, 2048, 512);

    // RoPE + concat into attention layout
    pack_q_kernel<<<(NM*NHID)/256, thr>>>();
    pack_k_kernel<<<(NM*NHID)/256, thr>>>();

    // fused causal flash attention (fp32)
    size_t smem = (size_t)(2*64*129 + 64*132 + 64*65) * sizeof(float);
    cudaFuncSetAttribute(flash_kernel, cudaFuncAttributeMaxDynamicSharedMemorySize, (int)smem);
    flash_kernel<<<dim3(NS/64, NH, NB), thr, smem>>>(Q, K, V, ctx);

    // split ctx, output projection + bias (tensor cores)
    run_split(ctx, ctxs, ctxs + XN, XN);
    bgemm_kernel<true><<<dim3(16, 64), thr, SMEM_BYTES>>>(ctxs, ctxs + XN, wos, wos + WO, out, bo, 2048, 2048);
}

// round 3
// speedup vs baseline: 2.6986x; 1.9047x over previous
#include <cuda_runtime.h>
#include <cuda_bf16.h>
#include <math.h>
#include <stdint.h>

using bf16 = __nv_bfloat16;

#define NB   4
#define NS   2048
#define NH   16
#define NHD  128
#define NRD  64
#define NLAT 512
#define NHID 2048
#define NM   (NB*NS)

__device__ float g_qlat [(size_t)NM*NLAT];
__device__ float g_kvlat[(size_t)NM*NLAT];
__device__ float g_krr  [(size_t)NM*NRD];
__device__ float g_qc   [(size_t)NM*1024];
__device__ float g_qr   [(size_t)NM*1024];
__device__ float g_kc   [(size_t)NM*1024];
__device__ float g_V    [(size_t)NM*NHID];
__device__ float g_ctx  [(size_t)NM*NHID];

__device__ bf16 g_xs   [2][(size_t)NM*NHID];
__device__ bf16 g_wqd_s[2][2048*512];
__device__ bf16 g_wkvd_s[2][2048*512];
__device__ bf16 g_wqu_s[2][512*1024];
__device__ bf16 g_wqr_s[2][512*1024];
__device__ bf16 g_wku_s[2][512*1024];
__device__ bf16 g_wvu_s[2][512*2048];
__device__ bf16 g_wo_s [2][2048*2048];
__device__ bf16 g_qlat_s[2][(size_t)NM*NLAT];
__device__ bf16 g_kvlat_s[2][(size_t)NM*NLAT];
__device__ bf16 g_ctx_s[2][(size_t)NM*NHID];

__device__ bf16 g_Qh[(size_t)NM*NHID];
__device__ bf16 g_Ql[(size_t)NM*NHID];
__device__ bf16 g_Kh[(size_t)NM*NHID];
__device__ bf16 g_Kl[(size_t)NM*NHID];
__device__ bf16 g_Vh[(size_t)NM*NHID];
__device__ bf16 g_Vl[(size_t)NM*NHID];

__global__ void split_kernel(const float* __restrict__ in,
                             bf16* __restrict__ hi, bf16* __restrict__ lo)
{
    size_t i = (size_t)blockIdx.x * blockDim.x + threadIdx.x;
    float f = in[i];
    bf16 h = __float2bfloat16(f);
    hi[i] = h;
    lo[i] = __float2bfloat16(f - __bfloat162float(h));
}

__device__ __forceinline__ void cp16(uint32_t s, const void* g) {
    asm volatile("cp.async.cg.shared.global [%0], [%1], 16;\n" :: "r"(s), "l"(g));
}

#define LDM_X4(R, addr) \
    asm volatile("ldmatrix.sync.aligned.m8n8.x4.shared.b16 {%0,%1,%2,%3}, [%4];" \
        : "=r"(R[0]), "=r"(R[1]), "=r"(R[2]), "=r"(R[3]) : "r"(addr))

#define LDM_X4_T(R, addr) \
    asm volatile("ldmatrix.sync.aligned.m8n8.x4.trans.shared.b16 {%0,%1,%2,%3}, [%4];" \
        : "=r"(R[0]), "=r"(R[1]), "=r"(R[2]), "=r"(R[3]) : "r"(addr))

#define MMA16816(D, A, B0, B1) \
    asm volatile("mma.sync.aligned.m16n8k16.row.col.f32.bf16.bf16.f32 " \
        "{%0,%1,%2,%3}, {%4,%5,%6,%7}, {%8,%9}, {%0,%1,%2,%3};" \
        : "+f"(D[0]), "+f"(D[1]), "+f"(D[2]), "+f"(D[3]) \
        : "r"(A[0]), "r"(A[1]), "r"(A[2]), "r"(A[3]), "r"(B0), "r"(B1))

__device__ __forceinline__ uint32_t pack_bf16(float lo_val, float hi_val) {
    uint32_t r;
    asm("cvt.rn.bf16x2.f32 %0, %1, %2;" : "=r"(r) : "f"(hi_val), "f"(lo_val));
    return r;
}

#define SA_ELEMS (128*40)
#define SB_ELEMS (32*136)
#define SMEM_BYTES ((4*SA_ELEMS + 4*SB_ELEMS)*2)

__device__ __forceinline__ void bgemm_fill(
    uint32_t smem_base, int buf,
    const bf16* __restrict__ Ah, const bf16* __restrict__ Al,
    const bf16* __restrict__ Bh, const bf16* __restrict__ Bl,
    int tid, int row0, int col0, int k0, int N, int K)
{
    #pragma unroll
    for (int c = 0; c < 2; c++) {
        int chunk = tid + 256*c;
        int r = chunk >> 2, cc = chunk & 3;
        size_t goff = (size_t)(row0 + r) * K + k0 + cc*8;
        uint32_t so = smem_base + (uint32_t)((buf*2+0)*SA_ELEMS + r*40 + cc*8)*2;
        cp16(so, Ah + goff);
        so = smem_base + (uint32_t)((buf*2+1)*SA_ELEMS + r*40 + cc*8)*2;
        cp16(so, Al + goff);
    }
    #pragma unroll
    for (int c = 0; c < 2; c++) {
        int chunk = tid + 256*c;
        int r = chunk >> 4, cc = chunk & 15;
        size_t goff = (size_t)(k0 + r) * N + col0 + cc*8;
        uint32_t so = smem_base + (uint32_t)(4*SA_ELEMS + (buf*2+0)*SB_ELEMS + r*136 + cc*8)*2;
        cp16(so, Bh + goff);
        so = smem_base + (uint32_t)(4*SA_ELEMS + (buf*2+1)*SB_ELEMS + r*136 + cc*8)*2;
        cp16(so, Bl + goff);
    }
    asm volatile("cp.async.commit_group;");
}

template<bool BIAS>
__global__ void __launch_bounds__(256, 1)
bgemm_kernel(const bf16* __restrict__ Ah, const bf16* __restrict__ Al,
             const bf16* __restrict__ Bh, const bf16* __restrict__ Bl,
             float* __restrict__ C, const float* __restrict__ bias,
             int N, int K)
{
    extern __shared__ bf16 smem_dyn[];
    const uint32_t smem_base = (uint32_t)__cvta_generic_to_shared(smem_dyn);

    const int tid  = threadIdx.x;
    const int lane = tid & 31;
    const int wid  = tid >> 5;
    const int m0w  = (wid >> 2) * 64;
    const int n0w  = (wid & 3) * 32;
    const int row0 = blockIdx.y * 128;
    const int col0 = blockIdx.x * 128;

    float acc[4][4][4];
    #pragma unroll
    for (int i = 0; i < 4; i++)
        #pragma unroll
        for (int j = 0; j < 4; j++)
            #pragma unroll
            for (int k = 0; k < 4; k++) acc[i][j][k] = 0.f;

    const int niter = K >> 5;
    bgemm_fill(smem_base, 0, Ah, Al, Bh, Bl, tid, row0, col0, 0, N, K);

    const int aRow  = m0w + (lane & 15);
    const int aCol8 = 8 * (lane >> 4);
    const int bRow  = lane & 15;
    const int bCol8 = n0w + 8 * (lane >> 4);

    for (int it = 0; it < niter; ++it) {
        const int buf = it & 1;
        if (it + 1 < niter) {
            bgemm_fill(smem_base, buf ^ 1, Ah, Al, Bh, Bl, tid, row0, col0, (it+1)*32, N, K);
            asm volatile("cp.async.wait_group 1;");
        } else {
            asm volatile("cp.async.wait_group 0;");
        }
        __syncthreads();

        #pragma unroll
        for (int sub = 0; sub < 32; sub += 16) {
            uint32_t ah[4][4], al[4][4];
            #pragma unroll
            for (int mt = 0; mt < 4; mt++) {
                uint32_t addr = smem_base +
                    (uint32_t)((buf*2)*SA_ELEMS + (aRow + mt*16)*40 + sub + aCol8)*2;
                LDM_X4(ah[mt], addr);
                addr += SA_ELEMS*2;
                LDM_X4(al[mt], addr);
            }
            uint32_t bh[2][4], bl[2][4];
            #pragma unroll
            for (int np = 0; np < 2; np++) {
                uint32_t addr = smem_base +
                    (uint32_t)(4*SA_ELEMS + (buf*2)*SB_ELEMS + (sub + bRow)*136 + bCol8 + np*16)*2;
                LDM_X4_T(bh[np], addr);
                addr += SB_ELEMS*2;
                LDM_X4_T(bl[np], addr);
            }
            #pragma unroll
            for (int mt = 0; mt < 4; mt++)
                #pragma unroll
                for (int nt = 0; nt < 4; nt++) {
                    uint32_t b0h = bh[nt>>1][(nt&1)*2], b1h = bh[nt>>1][(nt&1)*2+1];
                    uint32_t b0l = bl[nt>>1][(nt&1)*2], b1l = bl[nt>>1][(nt&1)*2+1];
                    MMA16816(acc[mt][nt], ah[mt], b0h, b1h);
                    MMA16816(acc[mt][nt], ah[mt], b0l, b1l);
                    MMA16816(acc[mt][nt], al[mt], b0h, b1h);
                }
        }
        __syncthreads();
    }

    #pragma unroll
    for (int mt = 0; mt < 4; mt++) {
        #pragma unroll
        for (int nt = 0; nt < 4; nt++) {
            int r  = row0 + m0w + mt*16 + (lane >> 2);
            int cc = col0 + n0w + nt*8 + (lane & 3)*2;
            float b0 = 0.f, b1 = 0.f;
            if (BIAS) { b0 = bias[cc]; b1 = bias[cc+1]; }
            float2 v0 = make_float2(acc[mt][nt][0] + b0, acc[mt][nt][1] + b1);
            float2 v1 = make_float2(acc[mt][nt][2] + b0, acc[mt][nt][3] + b1);
            *(float2*)(C + (size_t)r     * N + cc) = v0;
            *(float2*)(C + (size_t)(r+8) * N + cc) = v1;
        }
    }
}

template<bool BIAS>
__global__ void __launch_bounds__(256)
sgemm_kernel(const float* __restrict__ A, const float* __restrict__ W,
             float* __restrict__ C, const float* __restrict__ bias,
             int N, int K)
{
    __shared__ float As[16][132];
    __shared__ float Bs[16][128];

    const int tid = threadIdx.x;
    const int tx = tid & 15, ty = tid >> 4;
    const int bx = blockIdx.x, by = blockIdx.y;

    const int a_r = tid >> 2;
    const int a_c = (tid & 3) << 2;
    const int b_r = tid >> 5;
    const int b_c = (tid & 31) << 2;

    const float* Ab = A + (size_t)by * 128 * K;

    float acc[8][8];
    #pragma unroll
    for (int i = 0; i < 8; i++)
        #pragma unroll
        for (int j = 0; j < 8; j++) acc[i][j] = 0.f;

    for (int k0 = 0; k0 < K; k0 += 16) {
        #pragma unroll
        for (int u = 0; u < 2; u++) {
            int r = a_r + u*64;
            float4 v = *(const float4*)(Ab + (size_t)r * K + (k0 + a_c));
            As[a_c+0][r] = v.x; As[a_c+1][r] = v.y;
            As[a_c+2][r] = v.z; As[a_c+3][r] = v.w;
        }
        #pragma unroll
        for (int u = 0; u < 2; u++) {
            int r = b_r + u*8;
            int col = bx*128 + b_c;
            float4 v = make_float4(0.f, 0.f, 0.f, 0.f);
            if (col < N) v = *(const float4*)(W + (size_t)(k0 + r) * N + col);
            *(float4*)&Bs[r][b_c] = v;
        }
        __syncthreads();
        #pragma unroll
        for (int k = 0; k < 16; k++) {
            float a[8], b[8];
            *(float4*)&a[0] = *(const float4*)&As[k][ty*8];
            *(float4*)&a[4] = *(const float4*)&As[k][ty*8+4];
            *(float4*)&b[0] = *(const float4*)&Bs[k][tx*8];
            *(float4*)&b[4] = *(const float4*)&Bs[k][tx*8+4];
            #pragma unroll
            for (int i = 0; i < 8; i++)
                #pragma unroll
                for (int j = 0; j < 8; j++)
                    acc[i][j] = fmaf(a[i], b[j], acc[i][j]);
        }
        __syncthreads();
    }

    const int row0 = by*128 + ty*8;
    const int col0 = bx*128 + tx*8;
    #pragma unroll
    for (int i = 0; i < 8; i++) {
        #pragma unroll
        for (int j = 0; j < 8; j += 4) {
            int col = col0 + j;
            if (col < N) {
                float4 v = make_float4(acc[i][j], acc[i][j+1], acc[i][j+2], acc[i][j+3]);
                if (BIAS) {
                    v.x += bias[col+0]; v.y += bias[col+1];
                    v.z += bias[col+2]; v.w += bias[col+3];
                }
                *(float4*)(C + (size_t)(row0+i)*N + col) = v;
            }
        }
    }
}

__device__ __forceinline__ float rope_apply(const float* v32, int dd, int pos)
{
    int fi = dd & 31;
    float inv = powf(10000.f, -(float)(2*fi) / 64.f);
    float ang = (float)pos * inv;
    float cs = cosf(ang), sn = sinf(ang);
    float v = v32[dd];
    float w = (dd < 32) ? -v32[dd + 32] : v32[dd - 32];
    return v * cs + w * sn;
}

__global__ void pack_q_kernel()
{
    int idx = blockIdx.x * blockDim.x + threadIdx.x;
    int row = idx >> 11;
    int c   = idx & (NHID - 1);
    int h = c >> 7, d = c & 127;
    float out;
    if (d < 64) {
        out = g_qc[(size_t)row*1024 + h*64 + d];
    } else {
        const float* qr = g_qr + (size_t)row*1024 + h*64;
        out = rope_apply(qr, d - 64, row & (NS - 1));
    }
    out *= 0.08838834764831845f;
    bf16 hi = __float2bfloat16(out);
    g_Qh[idx] = hi;
    g_Ql[idx] = __float2bfloat16(out - __bfloat162float(hi));
}

__global__ void pack_k_kernel()
{
    int idx = blockIdx.x * blockDim.x + threadIdx.x;
    int row = idx >> 11;
    int c   = idx & (NHID - 1);
    int h = c >> 7, d = c & 127;
    float out;
    if (d < 64) {
        out = g_kc[(size_t)row*1024 + h*64 + d];
    } else {
        const float* kr = g_krr + (size_t)row*NRD;
        out = rope_apply(kr, d - 64, row & (NS - 1));
    }
    bf16 hi = __float2bfloat16(out);
    g_Kh[idx] = hi;
    g_Kl[idx] = __float2bfloat16(out - __bfloat162float(hi));
}

#define FS 136
#define FTILE_B (64*FS*2)

__global__ void __launch_bounds__(128)
flasht_kernel(const bf16* __restrict__ Qh, const bf16* __restrict__ Ql,
              const bf16* __restrict__ Kh, const bf16* __restrict__ Kl,
              const bf16* __restrict__ Vh, const bf16* __restrict__ Vl,
              float* __restrict__ O)
{
    extern __shared__ bf16 fsm[];
    const uint32_t sb = (uint32_t)__cvta_generic_to_shared(fsm);

    const int tid = threadIdx.x;
    const int lane = tid & 31;
    const int w = tid >> 5;
    const int lr = lane >> 2;
    const int lc = (lane & 3) * 2;
    const int h = blockIdx.y, b = blockIdx.z;
    const int q0 = blockIdx.x * 64;
    const size_t base = ((size_t)b * NS) * NHID + (size_t)h * NHD;

    for (int i = tid; i < 1024; i += 128) {
        int r = i >> 4, c = (i & 15) << 3;
        uint32_t so = (uint32_t)(r*FS + c) * 2;
        size_t go = base + (size_t)(q0 + r) * NHID + c;
        cp16(sb + 0*FTILE_B + so, Qh + go);
        cp16(sb + 1*FTILE_B + so, Ql + go);
    }
    asm volatile("cp.async.commit_group;");

    float m0 = -1e30f, m1 = -1e30f, l0 = 0.f, l1 = 0.f;
    float o[16][4];
    #pragma unroll
    for (int i = 0; i < 16; i++)
        #pragma unroll
        for (int j = 0; j < 4; j++) o[i][j] = 0.f;

    const int aRow = w*16 + (lane & 15);
    const int hi8  = 8 * (lane >> 4);
    const int ntiles = blockIdx.x + 1;

    for (int t = 0; t < ntiles; t++) {
        const int k0 = t * 64;
        if (t) __syncthreads();
        for (int i = tid; i < 1024; i += 128) {
            int r = i >> 4, c = (i & 15) << 3;
            uint32_t so = (uint32_t)(r*FS + c) * 2;
            size_t go = base + (size_t)(k0 + r) * NHID + c;
            cp16(sb + 2*FTILE_B + so, Kh + go);
            cp16(sb + 3*FTILE_B + so, Kl + go);
            cp16(sb + 4*FTILE_B + so, Vh + go);
            cp16(sb + 5*FTILE_B + so, Vl + go);
        }
        asm volatile("cp.async.commit_group;");
        asm volatile("cp.async.wait_group 0;");
        __syncthreads();

        float s[8][4];
        #pragma unroll
        for (int i = 0; i < 8; i++)
            #pragma unroll
            for (int j = 0; j < 4; j++) s[i][j] = 0.f;

        #pragma unroll
        for (int kc = 0; kc < 8; kc++) {
            uint32_t qh[4], ql[4];
            uint32_t qa = sb + (uint32_t)(aRow*FS + kc*16 + hi8)*2;
            LDM_X4(qh, qa);
            LDM_X4(ql, qa + FTILE_B);
            #pragma unroll
            for (int g = 0; g < 4; g++) {
                uint32_t kh[4], kl[4];
                uint32_t ka = sb + 2*FTILE_B + (uint32_t)((g*16 + (lane & 15))*FS + kc*16 + hi8)*2;
                LDM_X4(kh, ka);
                LDM_X4(kl, ka + FTILE_B);
                MMA16816(s[2*g],   qh, kh[0], kh[2]);
                MMA16816(s[2*g],   qh, kl[0], kl[2]);
                MMA16816(s[2*g],   ql, kh[0], kh[2]);
                MMA16816(s[2*g+1], qh, kh[1], kh[3]);
                MMA16816(s[2*g+1], qh, kl[1], kl[3]);
                MMA16816(s[2*g+1], ql, kh[1], kh[3]);
            }
        }

        if (t == blockIdx.x) {
            int r0 = q0 + w*16 + lr, r1 = r0 + 8;
            #pragma unroll
            for (int nt = 0; nt < 8; nt++) {
                int c = k0 + nt*8 + lc;
                if (c     > r0) s[nt][0] = -1e30f;
                if (c + 1 > r0) s[nt][1] = -1e30f;
                if (c     > r1) s[nt][2] = -1e30f;
                if (c + 1 > r1) s[nt][3] = -1e30f;
            }
        }

        float mt0 = -1e30f, mt1 = -1e30f;
        #pragma unroll
        for (int nt = 0; nt < 8; nt++) {
            mt0 = fmaxf(mt0, fmaxf(s[nt][0], s[nt][1]));
            mt1 = fmaxf(mt1, fmaxf(s[nt][2], s[nt][3]));
        }
        mt0 = fmaxf(mt0, __shfl_xor_sync(0xffffffffu, mt0, 1));
        mt0 = fmaxf(mt0, __shfl_xor_sync(0xffffffffu, mt0, 2));
        mt1 = fmaxf(mt1, __shfl_xor_sync(0xffffffffu, mt1, 1));
        mt1 = fmaxf(mt1, __shfl_xor_sync(0xffffffffu, mt1, 2));
        float n0 = fmaxf(m0, mt0), n1 = fmaxf(m1, mt1);
        float corr0 = __expf(m0 - n0), corr1 = __expf(m1 - n1);
        m0 = n0; m1 = n1;

        float ps0 = 0.f, ps1 = 0.f;
        #pragma unroll
        for (int nt = 0; nt < 8; nt++) {
            s[nt][0] = __expf(s[nt][0] - n0);
            s[nt][1] = __expf(s[nt][1] - n0);
            s[nt][2] = __expf(s[nt][2] - n1);
            s[nt][3] = __expf(s[nt][3] - n1);
            ps0 += s[nt][0] + s[nt][1];
            ps1 += s[nt][2] + s[nt][3];
        }
        l0 = l0 * corr0 + ps0;
        l1 = l1 * corr1 + ps1;
        #pragma unroll
        for (int i = 0; i < 16; i++) {
            o[i][0] *= corr0; o[i][1] *= corr0;
            o[i][2] *= corr1; o[i][3] *= corr1;
        }

        #pragma unroll
        for (int kc = 0; kc < 4; kc++) {
            uint32_t ph[4], pl[4];
            {
                float p00 = s[2*kc][0],   p01 = s[2*kc][1];
                float p02 = s[2*kc][2],   p03 = s[2*kc][3];
                float p10 = s[2*kc+1][0], p11 = s[2*kc+1][1];
                float p12 = s[2*kc+1][2], p13 = s[2*kc+1][3];
                bf16 h00 = __float2bfloat16(p00), h01 = __float2bfloat16(p01);
                bf16 h02 = __float2bfloat16(p02), h03 = __float2bfloat16(p03);
                bf16 h10 = __float2bfloat16(p10), h11 = __float2bfloat16(p11);
                bf16 h12 = __float2bfloat16(p12), h13 = __float2bfloat16(p13);
                ph[0] = pack_bf16(__bfloat162float(h00), __bfloat162float(h01));
                ph[1] = pack_bf16(__bfloat162float(h02), __bfloat162float(h03));
                ph[2] = pack_bf16(__bfloat162float(h10), __bfloat162float(h11));
                ph[3] = pack_bf16(__bfloat162float(h12), __bfloat162float(h13));
                pl[0] = pack_bf16(p00 - __bfloat162float(h00), p01 - __bfloat162float(h01));
                pl[1] = pack_bf16(p02 - __bfloat162float(h02), p03 - __bfloat162float(h03));
                pl[2] = pack_bf16(p10 - __bfloat162float(h10), p11 - __bfloat162float(h11));
                pl[3] = pack_bf16(p12 - __bfloat162float(h12), p13 - __bfloat162float(h13));
            }
            #pragma unroll
            for (int np = 0; np < 8; np++) {
                uint32_t vh[4], vl[4];
                uint32_t va = sb + 4*FTILE_B +
                    (uint32_t)((kc*16 + (lane & 15))*FS + np*16 + hi8)*2;
                LDM_X4_T(vh, va);
                LDM_X4_T(vl, va + FTILE_B);
                MMA16816(o[2*np],   ph, vh[0], vh[1]);
                MMA16816(o[2*np],   ph, vl[0], vl[1]);
                MMA16816(o[2*np],   pl, vh[0], vh[1]);
                MMA16816(o[2*np+1], ph, vh[2], vh[3]);
                MMA16816(o[2*np+1], ph, vl[2], vl[3]);
                MMA16816(o[2*np+1], pl, vh[2], vh[3]);
            }
        }
    }

    float t0 = l0, t1 = l1;
    t0 += __shfl_xor_sync(0xffffffffu, t0, 1);
    t0 += __shfl_xor_sync(0xffffffffu, t0, 2);
    t1 += __shfl_xor_sync(0xffffffffu, t1, 1);
    t1 += __shfl_xor_sync(0xffffffffu, t1, 2);
    float inv0 = 1.f / t0, inv1 = 1.f / t1;
    int r0 = q0 + w*16 + lr;
    #pragma unroll
    for (int nt = 0; nt < 16; nt++) {
        int c = nt*8 + lc;
        *(float2*)(O + base + (size_t)r0 * NHID + c) =
            make_float2(o[nt][0]*inv0, o[nt][1]*inv0);
        *(float2*)(O + base + (size_t)(r0+8) * NHID + c) =
            make_float2(o[nt][2]*inv1, o[nt][3]*inv1);
    }
}

static inline void run_split(const float* src, bf16* hi, bf16* lo, size_t n)
{
    split_kernel<<<(unsigned)(n / 256), 256>>>(src, hi, lo);
}

extern "C" void kernel_launch(void* const* d_in, const int* in_sizes, int n_in,
                              void* d_out, int out_size)
{
    const float* x        = (const float*)d_in[0];
    const float* wq_down  = (const float*)d_in[1];
    const float* wq_up    = (const float*)d_in[2];
    const float* wq_rope  = (const float*)d_in[3];
    const float* wk_rope  = (const float*)d_in[4];
    const float* wkv_down = (const float*)d_in[5];
    const float* wk_up    = (const float*)d_in[6];
    const float* wv_up    = (const float*)d_in[7];
    const float* wo       = (const float*)d_in[8];
    const float* bo       = (const float*)d_in[9];
    float* out = (float*)d_out;

    float *qlat, *kvlat, *krr, *qc, *qr, *kc, *V, *ctx;
    cudaGetSymbolAddress((void**)&qlat,  g_qlat);
    cudaGetSymbolAddress((void**)&kvlat, g_kvlat);
    cudaGetSymbolAddress((void**)&krr,   g_krr);
    cudaGetSymbolAddress((void**)&qc,    g_qc);
    cudaGetSymbolAddress((void**)&qr,    g_qr);
    cudaGetSymbolAddress((void**)&kc,    g_kc);
    cudaGetSymbolAddress((void**)&V,     g_V);
    cudaGetSymbolAddress((void**)&ctx,   g_ctx);

    bf16 *xs, *wqd, *wkvd, *wqu, *wqr, *wku, *wvu, *wos, *qls, *kvls, *ctxs;
    bf16 *Qh, *Ql, *Kh, *Kl, *Vh, *Vl;
    cudaGetSymbolAddress((void**)&xs,   g_xs);
    cudaGetSymbolAddress((void**)&wqd,  g_wqd_s);
    cudaGetSymbolAddress((void**)&wkvd, g_wkvd_s);
    cudaGetSymbolAddress((void**)&wqu,  g_wqu_s);
    cudaGetSymbolAddress((void**)&wqr,  g_wqr_s);
    cudaGetSymbolAddress((void**)&wku,  g_wku_s);
    cudaGetSymbolAddress((void**)&wvu,  g_wvu_s);
    cudaGetSymbolAddress((void**)&wos,  g_wo_s);
    cudaGetSymbolAddress((void**)&qls,  g_qlat_s);
    cudaGetSymbolAddress((void**)&kvls, g_kvlat_s);
    cudaGetSymbolAddress((void**)&ctxs, g_ctx_s);
    cudaGetSymbolAddress((void**)&Qh,   g_Qh);
    cudaGetSymbolAddress((void**)&Ql,   g_Ql);
    cudaGetSymbolAddress((void**)&Kh,   g_Kh);
    cudaGetSymbolAddress((void**)&Kl,   g_Kl);
    cudaGetSymbolAddress((void**)&Vh,   g_Vh);
    cudaGetSymbolAddress((void**)&Vl,   g_Vl);

    const size_t XN   = (size_t)NM*NHID;
    const size_t WD   = 2048*512;
    const size_t WU   = 512*1024;
    const size_t WV   = 512*2048;
    const size_t WO   = 2048*2048;
    const size_t QLN  = (size_t)NM*NLAT;

    cudaFuncSetAttribute(bgemm_kernel<false>, cudaFuncAttributeMaxDynamicSharedMemorySize, SMEM_BYTES);
    cudaFuncSetAttribute(bgemm_kernel<true>,  cudaFuncAttributeMaxDynamicSharedMemorySize, SMEM_BYTES);
    cudaFuncSetAttribute(flasht_kernel, cudaFuncAttributeMaxDynamicSharedMemorySize, 6*FTILE_B);

    dim3 thr(256);

    run_split(x,        xs,   xs + XN,  XN);
    run_split(wq_down,  wqd,  wqd + WD, WD);
    run_split(wkv_down, wkvd, wkvd + WD, WD);
    run_split(wq_up,    wqu,  wqu + WU, WU);
    run_split(wq_rope,  wqr,  wqr + WU, WU);
    run_split(wk_up,    wku,  wku + WU, WU);
    run_split(wv_up,    wvu,  wvu + WV, WV);
    run_split(wo,       wos,  wos + WO, WO);

    bgemm_kernel<false><<<dim3(4, 64), thr, SMEM_BYTES>>>(xs, xs + XN, wqd,  wqd + WD,  qlat,  nullptr, 512, 2048);
    bgemm_kernel<false><<<dim3(4, 64), thr, SMEM_BYTES>>>(xs, xs + XN, wkvd, wkvd + WD, kvlat, nullptr, 512, 2048);
    sgemm_kernel<false><<<dim3(1, 64), thr>>>(x, wk_rope, krr, nullptr, 64, 2048);

    run_split(qlat,  qls,  qls + QLN,  QLN);
    run_split(kvlat, kvls, kvls + QLN, QLN);

    bgemm_kernel<false><<<dim3(8, 64),  thr, SMEM_BYTES>>>(qls,  qls + QLN,  wqu, wqu + WU, qc, nullptr, 1024, 512);
    bgemm_kernel<false><<<dim3(8, 64),  thr, SMEM_BYTES>>>(qls,  qls + QLN,  wqr, wqr + WU, qr, nullptr, 1024, 512);
    bgemm_kernel<false><<<dim3(8, 64),  thr, SMEM_BYTES>>>(kvls, kvls + QLN, wku, wku + WU, kc, nullptr, 1024, 512);
    bgemm_kernel<false><<<dim3(16, 64), thr, SMEM_BYTES>>>(kvls, kvls + QLN, wvu, wvu + WV, V,  nullptr, 2048, 512);

    pack_q_kernel<<<(NM*NHID)/256, thr>>>();
    pack_k_kernel<<<(NM*NHID)/256, thr>>>();
    run_split(V, Vh, Vl, XN);

    flasht_kernel<<<dim3(NS/64, NH, NB), 128, 6*FTILE_B>>>(Qh, Ql, Kh, Kl, Vh, Vl, ctx);

    run_split(ctx, ctxs, ctxs + XN, XN);
    bgemm_kernel<true><<<dim3(16, 64), thr, SMEM_BYTES>>>(ctxs, ctxs + XN, wos, wos + WO, out, bo, 2048, 2048);
}